// round 4
// baseline (speedup 1.0000x reference)
#include <cuda_runtime.h>
#include <cuda_bf16.h>
#include <math.h>

// Problem constants (from reference): N=100000, H=128, E=500000, G=3
#define MAX_E      600000
#define CHUNK      128
#define MAX_CHUNKS ((MAX_E + CHUNK - 1) / CHUNK)

__device__ int d_perm[MAX_E];
__device__ int d_chunkCnt[MAX_CHUNKS * 3];
__device__ int d_chunkOff[MAX_CHUNKS * 3];
__device__ int d_groupStart[4];
__device__ int d_tileBase[4];

// ---------------------------------------------------------------------------
// Stable 3-way partition of edge indices by group.
// Output position of edge e == its rank in the stable partition == the slot
// required by argsort(groups, stable=True).
// ---------------------------------------------------------------------------

__global__ void k_count(const int* __restrict__ groups, int E, int nChunks) {
    int c = blockIdx.x * blockDim.x + threadIdx.x;
    if (c >= nChunks) return;
    int c0 = 0, c1 = 0, c2 = 0;
    int s = c * CHUNK, e = s + CHUNK; if (e > E) e = E;
    for (int i = s; i < e; i++) {
        int g = groups[i];
        c0 += (g == 0); c1 += (g == 1); c2 += (g == 2);
    }
    d_chunkCnt[c * 3 + 0] = c0;
    d_chunkCnt[c * 3 + 1] = c1;
    d_chunkCnt[c * 3 + 2] = c2;
}

#define SCAN_T 512

__global__ void k_scan(int nChunks) {
    __shared__ int sv[SCAN_T];
    __shared__ int gtot[3];
    __shared__ int gs[4];
    int tid = threadIdx.x;
    int per = (nChunks + SCAN_T - 1) / SCAN_T;
    int c0 = tid * per;
    int c1 = c0 + per; if (c1 > nChunks) c1 = nChunks;
    if (c0 > nChunks) c0 = nChunks;

    int t[3] = {0, 0, 0};
    for (int c = c0; c < c1; c++) {
        t[0] += d_chunkCnt[c * 3 + 0];
        t[1] += d_chunkCnt[c * 3 + 1];
        t[2] += d_chunkCnt[c * 3 + 2];
    }
    int base[3];
    for (int g = 0; g < 3; g++) {
        sv[tid] = t[g];
        __syncthreads();
        for (int off = 1; off < SCAN_T; off <<= 1) {
            int v = (tid >= off) ? sv[tid - off] : 0;
            __syncthreads();
            sv[tid] += v;
            __syncthreads();
        }
        base[g] = sv[tid] - t[g];                 // exclusive prefix
        if (tid == SCAN_T - 1) gtot[g] = sv[tid]; // total
        __syncthreads();
    }
    if (tid == 0) {
        gs[0] = 0;
        gs[1] = gtot[0];
        gs[2] = gtot[0] + gtot[1];
        gs[3] = gtot[0] + gtot[1] + gtot[2];
        int tb = 0;
        for (int g = 0; g < 3; g++) {
            d_groupStart[g] = gs[g];
            d_tileBase[g] = tb;
            tb += (gtot[g] + 63) >> 6;
        }
        d_groupStart[3] = gs[3];
        d_tileBase[3] = tb;
    }
    __syncthreads();
    int run[3];
    for (int g = 0; g < 3; g++) run[g] = gs[g] + base[g];
    for (int c = c0; c < c1; c++) {
        for (int g = 0; g < 3; g++) {
            d_chunkOff[c * 3 + g] = run[g];
            run[g] += d_chunkCnt[c * 3 + g];
        }
    }
}

__global__ void k_scatter(const int* __restrict__ groups, int E, int nChunks) {
    int c = blockIdx.x * blockDim.x + threadIdx.x;
    if (c >= nChunks) return;
    int o0 = d_chunkOff[c * 3 + 0];
    int o1 = d_chunkOff[c * 3 + 1];
    int o2 = d_chunkOff[c * 3 + 2];
    int s = c * CHUNK, e = s + CHUNK; if (e > E) e = E;
    for (int i = s; i < e; i++) {
        int g = groups[i];
        int p = (g == 0) ? o0++ : (g == 1) ? o1++ : o2++;
        d_perm[p] = i;
    }
}

// ---------------------------------------------------------------------------
// Main fused kernel: one CTA per 64-edge tile of a single group.
//   GEMM1 [64,256]x[256,128] -> +b1 -> LayerNorm -> GELU(exact)
//   GEMM2 [64,128]x[128,64]  -> +b2 -> GELU(exact)
//   s = h2 . W3[g] + b3[g]   -> out[tileStart + row]
// 256 threads, thread tile: GEMM1 4 edges x 8 outs, GEMM2 4 edges x 4 outs.
// ---------------------------------------------------------------------------

__global__ __launch_bounds__(256) void k_main(
    const float* __restrict__ emb, const int* __restrict__ edges,
    const float* __restrict__ W1, const float* __restrict__ b1,
    const float* __restrict__ lng, const float* __restrict__ lnb,
    const float* __restrict__ W2, const float* __restrict__ b2,
    const float* __restrict__ W3, const float* __restrict__ b3,
    float* __restrict__ out)
{
    __shared__ __align__(16) union {
        struct { float ee[64 * 36]; float w1[32 * 132]; } p1;  // 26.1 KB
        struct { float h[64 * 132]; float w2[32 * 68]; } p2;   // 42.5 KB
    } sm;
    __shared__ int sU[64], sV[64];

    int b = blockIdx.x;
    if (b >= d_tileBase[3]) return;
    int g = (b >= d_tileBase[1]) + (b >= d_tileBase[2]);
    int tileInG = b - d_tileBase[g];
    int tileStart = d_groupStart[g] + tileInG * 64;
    int nE = d_groupStart[g + 1] - tileStart;
    if (nE > 64) nE = 64;

    int tid = threadIdx.x;
    if (tid < 64) {
        int u = 0, v = 0;
        if (tid < nE) {
            int e = d_perm[tileStart + tid];
            u = edges[2 * e];
            v = edges[2 * e + 1];
        }
        sU[tid] = u; sV[tid] = v;
    }
    __syncthreads();

    const int tx = tid & 15, ty = tid >> 4;

    float acc[4][8];
#pragma unroll
    for (int i = 0; i < 4; i++)
#pragma unroll
        for (int j = 0; j < 8; j++) acc[i][j] = 0.f;

    const float* W1g = W1 + (size_t)g * 256 * 128;

    // ---- GEMM1: K = 256 (dims 0-127 from u, 128-255 from v), BK = 32 ----
    for (int kb = 0; kb < 256; kb += 32) {
        // ee tile: 64 rows x 32 cols = 512 float4 (2 per thread)
#pragma unroll
        for (int t = 0; t < 2; t++) {
            int idx = tid + t * 256;        // 0..511
            int r = idx >> 3, q = idx & 7;  // row 0..63, q 0..7
            int node = (kb < 128) ? sU[r] : sV[r];
            int cb = (kb & 127) + q * 4;
            float4 val = *(const float4*)(emb + (size_t)node * 128 + cb);
            *(float4*)(&sm.p1.ee[r * 36 + q * 4]) = val;
        }
        // W1 tile: 32 rows x 128 cols = 1024 float4 (4 per thread)
#pragma unroll
        for (int t = 0; t < 4; t++) {
            int idx = tid + t * 256;          // 0..1023
            int rr = idx >> 5, q = idx & 31;  // rr 0..31, q 0..31
            float4 val = *(const float4*)(W1g + (size_t)(kb + rr) * 128 + q * 4);
            *(float4*)(&sm.p1.w1[rr * 132 + q * 4]) = val;
        }
        __syncthreads();

#pragma unroll
        for (int kk4 = 0; kk4 < 32; kk4 += 4) {
            float4 a4[4];
#pragma unroll
            for (int i = 0; i < 4; i++)
                a4[i] = *(const float4*)(&sm.p1.ee[(ty * 4 + i) * 36 + kk4]);
            const float* ap = reinterpret_cast<const float*>(a4);
#pragma unroll
            for (int u = 0; u < 4; u++) {
                float4 b0 = *(const float4*)(&sm.p1.w1[(kk4 + u) * 132 + tx * 8]);
                float4 b1v = *(const float4*)(&sm.p1.w1[(kk4 + u) * 132 + tx * 8 + 4]);
#pragma unroll
                for (int i = 0; i < 4; i++) {
                    float av = ap[i * 4 + u];
                    acc[i][0] = fmaf(av, b0.x,  acc[i][0]);
                    acc[i][1] = fmaf(av, b0.y,  acc[i][1]);
                    acc[i][2] = fmaf(av, b0.z,  acc[i][2]);
                    acc[i][3] = fmaf(av, b0.w,  acc[i][3]);
                    acc[i][4] = fmaf(av, b1v.x, acc[i][4]);
                    acc[i][5] = fmaf(av, b1v.y, acc[i][5]);
                    acc[i][6] = fmaf(av, b1v.z, acc[i][6]);
                    acc[i][7] = fmaf(av, b1v.w, acc[i][7]);
                }
            }
        }
        __syncthreads();
    }

    // ---- bias + LayerNorm + exact GELU (reductions over 16-lane groups) ----
    float bb1[8], lgv[8], lbv[8];
#pragma unroll
    for (int j = 0; j < 8; j++) {
        int o = tx * 8 + j;
        bb1[j] = b1[g * 128 + o];
        lgv[j] = lng[g * 128 + o];
        lbv[j] = lnb[g * 128 + o];
    }
#pragma unroll
    for (int i = 0; i < 4; i++) {
        float s = 0.f, s2 = 0.f;
#pragma unroll
        for (int j = 0; j < 8; j++) {
            float h = acc[i][j] + bb1[j];
            acc[i][j] = h;
            s += h; s2 += h * h;
        }
#pragma unroll
        for (int m = 1; m < 16; m <<= 1) {
            s  += __shfl_xor_sync(0xffffffffu, s,  m);
            s2 += __shfl_xor_sync(0xffffffffu, s2, m);
        }
        float mu  = s * (1.f / 128.f);
        float var = s2 * (1.f / 128.f) - mu * mu;
        float inv = rsqrtf(var + 1e-5f);
#pragma unroll
        for (int j = 0; j < 8; j++) {
            float hn = (acc[i][j] - mu) * inv * lgv[j] + lbv[j];
            acc[i][j] = hn * normcdff(hn);   // exact gelu: x * Phi(x)
        }
    }

    // stash h into smem (phase-1 buffers are dead past the last sync)
#pragma unroll
    for (int i = 0; i < 4; i++)
#pragma unroll
        for (int j = 0; j < 8; j++)
            sm.p2.h[(ty * 4 + i) * 132 + tx * 8 + j] = acc[i][j];

    // ---- GEMM2: [64,128] x [128,64], BK = 32 ----
    const float* W2g = W2 + (size_t)g * 128 * 64;
    float c2[4][4];
#pragma unroll
    for (int i = 0; i < 4; i++)
#pragma unroll
        for (int j = 0; j < 4; j++) c2[i][j] = 0.f;

    for (int kb = 0; kb < 128; kb += 32) {
        __syncthreads();  // protects w2 reuse; first iter also orders h writes
#pragma unroll
        for (int t = 0; t < 2; t++) {
            int idx = tid + t * 256;           // 0..511
            int rr = idx >> 4, q = idx & 15;   // rr 0..31, q 0..15
            float4 val = *(const float4*)(W2g + (size_t)(kb + rr) * 64 + q * 4);
            *(float4*)(&sm.p2.w2[rr * 68 + q * 4]) = val;
        }
        __syncthreads();

#pragma unroll
        for (int kk4 = 0; kk4 < 32; kk4 += 4) {
            float4 a4[4];
#pragma unroll
            for (int i = 0; i < 4; i++)
                a4[i] = *(const float4*)(&sm.p2.h[(ty * 4 + i) * 132 + kb + kk4]);
            const float* ap = reinterpret_cast<const float*>(a4);
#pragma unroll
            for (int u = 0; u < 4; u++) {
                float4 bv = *(const float4*)(&sm.p2.w2[(kk4 + u) * 68 + tx * 4]);
#pragma unroll
                for (int i = 0; i < 4; i++) {
                    float av = ap[i * 4 + u];
                    c2[i][0] = fmaf(av, bv.x, c2[i][0]);
                    c2[i][1] = fmaf(av, bv.y, c2[i][1]);
                    c2[i][2] = fmaf(av, bv.z, c2[i][2]);
                    c2[i][3] = fmaf(av, bv.w, c2[i][3]);
                }
            }
        }
    }

    // ---- bias + GELU + dot W3 + b3, 16-lane reduce, write ----
    float bb2[4], w3v[4];
#pragma unroll
    for (int j = 0; j < 4; j++) {
        bb2[j] = b2[g * 64 + tx * 4 + j];
        w3v[j] = W3[g * 64 + tx * 4 + j];
    }
    float b3v = b3[g];
#pragma unroll
    for (int i = 0; i < 4; i++) {
        float p = 0.f;
#pragma unroll
        for (int j = 0; j < 4; j++) {
            float x = c2[i][j] + bb2[j];
            float gx = x * normcdff(x);
            p = fmaf(gx, w3v[j], p);
        }
#pragma unroll
        for (int m = 1; m < 16; m <<= 1)
            p += __shfl_xor_sync(0xffffffffu, p, m);
        int r = ty * 4 + i;
        if (tx == 0 && r < nE) out[tileStart + r] = p + b3v;
    }
}

// ---------------------------------------------------------------------------

extern "C" void kernel_launch(void* const* d_in, const int* in_sizes, int n_in,
                              void* d_out, int out_size) {
    const float* emb    = (const float*)d_in[0];
    const int*   edges  = (const int*)d_in[1];
    const int*   groups = (const int*)d_in[2];
    const float* W1     = (const float*)d_in[3];
    const float* b1     = (const float*)d_in[4];
    const float* lng    = (const float*)d_in[5];
    const float* lnb    = (const float*)d_in[6];
    const float* W2     = (const float*)d_in[7];
    const float* b2     = (const float*)d_in[8];
    const float* W3     = (const float*)d_in[9];
    const float* b3     = (const float*)d_in[10];
    float* out = (float*)d_out;

    int E = in_sizes[2];               // groups element count == E
    int nChunks = (E + CHUNK - 1) / CHUNK;

    k_count<<<(nChunks + 255) / 256, 256>>>(groups, E, nChunks);
    k_scan<<<1, SCAN_T>>>(nChunks);
    k_scatter<<<(nChunks + 255) / 256, 256>>>(groups, E, nChunks);

    int maxTiles = (E + 63) / 64 + 3;  // upper bound; extra CTAs exit early
    k_main<<<maxTiles, 256>>>(emb, edges, W1, b1, lng, lnb, W2, b2, W3, b3, out);
}

// round 5
// speedup vs baseline: 1.2835x; 1.2835x over previous
#include <cuda_runtime.h>
#include <cuda_bf16.h>
#include <math.h>

// Problem constants (from reference): N=100000, H=128, E=500000, G=3
#define MAX_E      600000
#define CHUNK      128
#define MAX_CHUNKS ((MAX_E + CHUNK - 1) / CHUNK)

__device__ int d_perm[MAX_E];
__device__ int d_chunkCnt[MAX_CHUNKS * 3];
__device__ int d_chunkOff[MAX_CHUNKS * 3];
__device__ int d_groupStart[4];
__device__ int d_tileBase[4];

// ---- packed f32x2 helpers (Blackwell sm_100+) ------------------------------
__device__ __forceinline__ unsigned long long pack2(float x) {
    unsigned long long r;
    asm("mov.b64 %0, {%1, %1};" : "=l"(r) : "f"(x));
    return r;
}
__device__ __forceinline__ void ffma2(unsigned long long& d,
                                      unsigned long long a,
                                      unsigned long long b) {
    asm("fma.rn.f32x2 %0, %1, %2, %0;" : "+l"(d) : "l"(a), "l"(b));
}
__device__ __forceinline__ float2 unpack2(unsigned long long v) {
    float2 f;
    asm("mov.b64 {%0, %1}, %2;" : "=f"(f.x), "=f"(f.y) : "l"(v));
    return f;
}

// ---------------------------------------------------------------------------
// Stable 3-way partition of edge indices by group.
// ---------------------------------------------------------------------------

__global__ void k_count(const int* __restrict__ groups, int E, int nChunks) {
    int c = blockIdx.x * blockDim.x + threadIdx.x;
    if (c >= nChunks) return;
    int c0 = 0, c1 = 0, c2 = 0;
    int s = c * CHUNK, e = s + CHUNK; if (e > E) e = E;
    for (int i = s; i < e; i++) {
        int g = groups[i];
        c0 += (g == 0); c1 += (g == 1); c2 += (g == 2);
    }
    d_chunkCnt[c * 3 + 0] = c0;
    d_chunkCnt[c * 3 + 1] = c1;
    d_chunkCnt[c * 3 + 2] = c2;
}

#define SCAN_T 512

__global__ void k_scan(int nChunks) {
    __shared__ int sv[SCAN_T];
    __shared__ int gtot[3];
    __shared__ int gs[4];
    int tid = threadIdx.x;
    int per = (nChunks + SCAN_T - 1) / SCAN_T;
    int c0 = tid * per;
    int c1 = c0 + per; if (c1 > nChunks) c1 = nChunks;
    if (c0 > nChunks) c0 = nChunks;

    int t[3] = {0, 0, 0};
    for (int c = c0; c < c1; c++) {
        t[0] += d_chunkCnt[c * 3 + 0];
        t[1] += d_chunkCnt[c * 3 + 1];
        t[2] += d_chunkCnt[c * 3 + 2];
    }
    int base[3];
    for (int g = 0; g < 3; g++) {
        sv[tid] = t[g];
        __syncthreads();
        for (int off = 1; off < SCAN_T; off <<= 1) {
            int v = (tid >= off) ? sv[tid - off] : 0;
            __syncthreads();
            sv[tid] += v;
            __syncthreads();
        }
        base[g] = sv[tid] - t[g];
        if (tid == SCAN_T - 1) gtot[g] = sv[tid];
        __syncthreads();
    }
    if (tid == 0) {
        gs[0] = 0;
        gs[1] = gtot[0];
        gs[2] = gtot[0] + gtot[1];
        gs[3] = gtot[0] + gtot[1] + gtot[2];
        int tb = 0;
        for (int g = 0; g < 3; g++) {
            d_groupStart[g] = gs[g];
            d_tileBase[g] = tb;
            tb += (gtot[g] + 63) >> 6;
        }
        d_groupStart[3] = gs[3];
        d_tileBase[3] = tb;
    }
    __syncthreads();
    int run[3];
    for (int g = 0; g < 3; g++) run[g] = gs[g] + base[g];
    for (int c = c0; c < c1; c++) {
        for (int g = 0; g < 3; g++) {
            d_chunkOff[c * 3 + g] = run[g];
            run[g] += d_chunkCnt[c * 3 + g];
        }
    }
}

__global__ void k_scatter(const int* __restrict__ groups, int E, int nChunks) {
    int c = blockIdx.x * blockDim.x + threadIdx.x;
    if (c >= nChunks) return;
    int o0 = d_chunkOff[c * 3 + 0];
    int o1 = d_chunkOff[c * 3 + 1];
    int o2 = d_chunkOff[c * 3 + 2];
    int s = c * CHUNK, e = s + CHUNK; if (e > E) e = E;
    for (int i = s; i < e; i++) {
        int g = groups[i];
        int p = (g == 0) ? o0++ : (g == 1) ? o1++ : o2++;
        d_perm[p] = i;
    }
}

// ---------------------------------------------------------------------------
// Main fused kernel. One CTA per 64-edge tile.
// Column mapping per thread (conflict-free): GEMM1 cols {tx*4..+3, 64+tx*4..+3};
// GEMM2 cols {tx*4..+3}. Inner product uses packed fma.rn.f32x2.
// ---------------------------------------------------------------------------

__global__ __launch_bounds__(256) void k_main(
    const float* __restrict__ emb, const int* __restrict__ edges,
    const float* __restrict__ W1, const float* __restrict__ b1,
    const float* __restrict__ lng, const float* __restrict__ lnb,
    const float* __restrict__ W2, const float* __restrict__ b2,
    const float* __restrict__ W3, const float* __restrict__ b3,
    float* __restrict__ out)
{
    __shared__ __align__(16) union {
        struct { float ee[64 * 36]; float w1[32 * 132]; } p1;  // 26.1 KB
        struct { float h[64 * 132]; float w2[32 * 68]; } p2;   // 42.5 KB
    } sm;
    __shared__ int sU[64], sV[64];

    int b = blockIdx.x;
    if (b >= d_tileBase[3]) return;
    int g = (b >= d_tileBase[1]) + (b >= d_tileBase[2]);
    int tileInG = b - d_tileBase[g];
    int tileStart = d_groupStart[g] + tileInG * 64;
    int nE = d_groupStart[g + 1] - tileStart;
    if (nE > 64) nE = 64;

    int tid = threadIdx.x;
    if (tid < 64) {
        int u = 0, v = 0;
        if (tid < nE) {
            int e = d_perm[tileStart + tid];
            u = edges[2 * e];
            v = edges[2 * e + 1];
        }
        sU[tid] = u; sV[tid] = v;
    }
    __syncthreads();

    const int tx = tid & 15, ty = tid >> 4;

    // acc2[i][p]: rows ty*4+i; pairs p: 0,1 -> cols tx*4+{0,1},{2,3};
    //                                p: 2,3 -> cols 64+tx*4+{0,1},{2,3}
    unsigned long long acc2[4][4];
#pragma unroll
    for (int i = 0; i < 4; i++)
#pragma unroll
        for (int p = 0; p < 4; p++) acc2[i][p] = 0ull;

    const float* W1g = W1 + (size_t)g * 256 * 128;

    // ---- GEMM1: K = 256 (dims 0-127 from u, 128-255 from v), BK = 32 ----
    for (int kb = 0; kb < 256; kb += 32) {
#pragma unroll
        for (int t = 0; t < 2; t++) {
            int idx = tid + t * 256;
            int r = idx >> 3, q = idx & 7;
            int node = (kb < 128) ? sU[r] : sV[r];
            int cb = (kb & 127) + q * 4;
            float4 val = *(const float4*)(emb + (size_t)node * 128 + cb);
            *(float4*)(&sm.p1.ee[r * 36 + q * 4]) = val;
        }
#pragma unroll
        for (int t = 0; t < 4; t++) {
            int idx = tid + t * 256;
            int rr = idx >> 5, q = idx & 31;
            float4 val = *(const float4*)(W1g + (size_t)(kb + rr) * 128 + q * 4);
            *(float4*)(&sm.p1.w1[rr * 132 + q * 4]) = val;
        }
        __syncthreads();

#pragma unroll
        for (int kk4 = 0; kk4 < 32; kk4 += 4) {
            float4 a4[4];
#pragma unroll
            for (int i = 0; i < 4; i++)
                a4[i] = *(const float4*)(&sm.p1.ee[(ty * 4 + i) * 36 + kk4]);
            const float* ap = reinterpret_cast<const float*>(a4);
#pragma unroll
            for (int u = 0; u < 4; u++) {
                ulonglong2 bA = *(const ulonglong2*)(&sm.p1.w1[(kk4 + u) * 132 + tx * 4]);
                ulonglong2 bB = *(const ulonglong2*)(&sm.p1.w1[(kk4 + u) * 132 + 64 + tx * 4]);
#pragma unroll
                for (int i = 0; i < 4; i++) {
                    unsigned long long pa = pack2(ap[i * 4 + u]);
                    ffma2(acc2[i][0], pa, bA.x);
                    ffma2(acc2[i][1], pa, bA.y);
                    ffma2(acc2[i][2], pa, bB.x);
                    ffma2(acc2[i][3], pa, bB.y);
                }
            }
        }
        __syncthreads();
    }

    // ---- bias + LayerNorm + exact GELU ----
    // col(j): j<4 -> tx*4+j ; j>=4 -> 64+tx*4+(j-4)
    float bb1[8], lgv[8], lbv[8];
#pragma unroll
    for (int j = 0; j < 8; j++) {
        int o = (j < 4) ? (tx * 4 + j) : (64 + tx * 4 + (j - 4));
        bb1[j] = b1[g * 128 + o];
        lgv[j] = lng[g * 128 + o];
        lbv[j] = lnb[g * 128 + o];
    }
#pragma unroll
    for (int i = 0; i < 4; i++) {
        float hv[8];
#pragma unroll
        for (int p = 0; p < 4; p++) {
            float2 f = unpack2(acc2[i][p]);
            hv[p * 2] = f.x; hv[p * 2 + 1] = f.y;
        }
        float s = 0.f, s2 = 0.f;
#pragma unroll
        for (int j = 0; j < 8; j++) {
            float h = hv[j] + bb1[j];
            hv[j] = h;
            s += h; s2 += h * h;
        }
#pragma unroll
        for (int m = 1; m < 16; m <<= 1) {
            s  += __shfl_xor_sync(0xffffffffu, s,  m);
            s2 += __shfl_xor_sync(0xffffffffu, s2, m);
        }
        float mu  = s * (1.f / 128.f);
        float var = s2 * (1.f / 128.f) - mu * mu;
        float inv = rsqrtf(var + 1e-5f);
        float4 outA, outB;
        float* oa = reinterpret_cast<float*>(&outA);
        float* ob = reinterpret_cast<float*>(&outB);
#pragma unroll
        for (int j = 0; j < 8; j++) {
            float hn = (hv[j] - mu) * inv * lgv[j] + lbv[j];
            float gv = hn * normcdff(hn);      // exact gelu: x * Phi(x)
            if (j < 4) oa[j] = gv; else ob[j - 4] = gv;
        }
        int row = ty * 4 + i;
        *(float4*)(&sm.p2.h[row * 132 + tx * 4]) = outA;
        *(float4*)(&sm.p2.h[row * 132 + 64 + tx * 4]) = outB;
    }

    // ---- GEMM2: [64,128] x [128,64], BK = 32, cols tx*4..+3 ----
    const float* W2g = W2 + (size_t)g * 128 * 64;
    unsigned long long c2[4][2];
#pragma unroll
    for (int i = 0; i < 4; i++) { c2[i][0] = 0ull; c2[i][1] = 0ull; }

    for (int kb = 0; kb < 128; kb += 32) {
        __syncthreads();  // protects w2 reuse; first iter also orders h writes
#pragma unroll
        for (int t = 0; t < 2; t++) {
            int idx = tid + t * 256;
            int rr = idx >> 4, q = idx & 15;
            float4 val = *(const float4*)(W2g + (size_t)(kb + rr) * 64 + q * 4);
            *(float4*)(&sm.p2.w2[rr * 68 + q * 4]) = val;
        }
        __syncthreads();

#pragma unroll
        for (int kk4 = 0; kk4 < 32; kk4 += 4) {
            float4 a4[4];
#pragma unroll
            for (int i = 0; i < 4; i++)
                a4[i] = *(const float4*)(&sm.p2.h[(ty * 4 + i) * 132 + kb + kk4]);
            const float* ap = reinterpret_cast<const float*>(a4);
#pragma unroll
            for (int u = 0; u < 4; u++) {
                ulonglong2 bv = *(const ulonglong2*)(&sm.p2.w2[(kk4 + u) * 68 + tx * 4]);
#pragma unroll
                for (int i = 0; i < 4; i++) {
                    unsigned long long pa = pack2(ap[i * 4 + u]);
                    ffma2(c2[i][0], pa, bv.x);
                    ffma2(c2[i][1], pa, bv.y);
                }
            }
        }
    }

    // ---- bias + GELU + dot W3 + b3, 16-lane reduce, write ----
    float bb2[4], w3v[4];
#pragma unroll
    for (int j = 0; j < 4; j++) {
        bb2[j] = b2[g * 64 + tx * 4 + j];
        w3v[j] = W3[g * 64 + tx * 4 + j];
    }
    float b3v = b3[g];
#pragma unroll
    for (int i = 0; i < 4; i++) {
        float hv[4];
        float2 f0 = unpack2(c2[i][0]);
        float2 f1 = unpack2(c2[i][1]);
        hv[0] = f0.x; hv[1] = f0.y; hv[2] = f1.x; hv[3] = f1.y;
        float p = 0.f;
#pragma unroll
        for (int j = 0; j < 4; j++) {
            float x = hv[j] + bb2[j];
            float gx = x * normcdff(x);
            p = fmaf(gx, w3v[j], p);
        }
#pragma unroll
        for (int m = 1; m < 16; m <<= 1)
            p += __shfl_xor_sync(0xffffffffu, p, m);
        int r = ty * 4 + i;
        if (tx == 0 && r < nE) out[tileStart + r] = p + b3v;
    }
}

// ---------------------------------------------------------------------------

extern "C" void kernel_launch(void* const* d_in, const int* in_sizes, int n_in,
                              void* d_out, int out_size) {
    const float* emb    = (const float*)d_in[0];
    const int*   edges  = (const int*)d_in[1];
    const int*   groups = (const int*)d_in[2];
    const float* W1     = (const float*)d_in[3];
    const float* b1     = (const float*)d_in[4];
    const float* lng    = (const float*)d_in[5];
    const float* lnb    = (const float*)d_in[6];
    const float* W2     = (const float*)d_in[7];
    const float* b2     = (const float*)d_in[8];
    const float* W3     = (const float*)d_in[9];
    const float* b3     = (const float*)d_in[10];
    float* out = (float*)d_out;

    int E = in_sizes[2];
    int nChunks = (E + CHUNK - 1) / CHUNK;

    k_count<<<(nChunks + 255) / 256, 256>>>(groups, E, nChunks);
    k_scan<<<1, SCAN_T>>>(nChunks);
    k_scatter<<<(nChunks + 255) / 256, 256>>>(groups, E, nChunks);

    int maxTiles = (E + 63) / 64 + 3;
    k_main<<<maxTiles, 256>>>(emb, edges, W1, b1, lng, lnb, W2, b2, W3, b3, out);
}

// round 7
// speedup vs baseline: 1.3197x; 1.0282x over previous
#include <cuda_runtime.h>
#include <cuda_bf16.h>
#include <math.h>

// Problem constants (from reference): N=100000, H=128, E=500000, G=3
#define MAX_E      600000
#define CHUNK      128
#define MAX_CHUNKS ((MAX_E + CHUNK - 1) / CHUNK)

__device__ int d_perm[MAX_E];
__device__ int d_chunkCnt[MAX_CHUNKS * 3];
__device__ int d_chunkOff[MAX_CHUNKS * 3];
__device__ int d_groupStart[4];
__device__ int d_tileBase[4];

// ---- packed f32x2 helpers (Blackwell sm_100+) ------------------------------
__device__ __forceinline__ unsigned long long pack2(float x) {
    unsigned long long r;
    asm("mov.b64 %0, {%1, %1};" : "=l"(r) : "f"(x));
    return r;
}
__device__ __forceinline__ void ffma2(unsigned long long& d,
                                      unsigned long long a,
                                      unsigned long long b) {
    asm("fma.rn.f32x2 %0, %1, %2, %0;" : "+l"(d) : "l"(a), "l"(b));
}
__device__ __forceinline__ float2 unpack2(unsigned long long v) {
    float2 f;
    asm("mov.b64 {%0, %1}, %2;" : "=f"(f.x), "=f"(f.y) : "l"(v));
    return f;
}

// ---------------------------------------------------------------------------
// Stable 3-way partition of edge indices by group (64-edge tiles).
// ---------------------------------------------------------------------------

__global__ void k_count(const int* __restrict__ groups, int E, int nChunks) {
    int c = blockIdx.x * blockDim.x + threadIdx.x;
    if (c >= nChunks) return;
    int c0 = 0, c1 = 0, c2 = 0;
    int s = c * CHUNK, e = s + CHUNK; if (e > E) e = E;
    for (int i = s; i < e; i++) {
        int g = groups[i];
        c0 += (g == 0); c1 += (g == 1); c2 += (g == 2);
    }
    d_chunkCnt[c * 3 + 0] = c0;
    d_chunkCnt[c * 3 + 1] = c1;
    d_chunkCnt[c * 3 + 2] = c2;
}

#define SCAN_T 512

__global__ void k_scan(int nChunks) {
    __shared__ int sv[SCAN_T];
    __shared__ int gtot[3];
    __shared__ int gs[4];
    int tid = threadIdx.x;
    int per = (nChunks + SCAN_T - 1) / SCAN_T;
    int c0 = tid * per;
    int c1 = c0 + per; if (c1 > nChunks) c1 = nChunks;
    if (c0 > nChunks) c0 = nChunks;

    int t[3] = {0, 0, 0};
    for (int c = c0; c < c1; c++) {
        t[0] += d_chunkCnt[c * 3 + 0];
        t[1] += d_chunkCnt[c * 3 + 1];
        t[2] += d_chunkCnt[c * 3 + 2];
    }
    int base[3];
    for (int g = 0; g < 3; g++) {
        sv[tid] = t[g];
        __syncthreads();
        for (int off = 1; off < SCAN_T; off <<= 1) {
            int v = (tid >= off) ? sv[tid - off] : 0;
            __syncthreads();
            sv[tid] += v;
            __syncthreads();
        }
        base[g] = sv[tid] - t[g];
        if (tid == SCAN_T - 1) gtot[g] = sv[tid];
        __syncthreads();
    }
    if (tid == 0) {
        gs[0] = 0;
        gs[1] = gtot[0];
        gs[2] = gtot[0] + gtot[1];
        gs[3] = gtot[0] + gtot[1] + gtot[2];
        int tb = 0;
        for (int g = 0; g < 3; g++) {
            d_groupStart[g] = gs[g];
            d_tileBase[g] = tb;
            tb += (gtot[g] + 63) >> 6;     // 64-edge tiles
        }
        d_groupStart[3] = gs[3];
        d_tileBase[3] = tb;
    }
    __syncthreads();
    int run[3];
    for (int g = 0; g < 3; g++) run[g] = gs[g] + base[g];
    for (int c = c0; c < c1; c++) {
        for (int g = 0; g < 3; g++) {
            d_chunkOff[c * 3 + g] = run[g];
            run[g] += d_chunkCnt[c * 3 + g];
        }
    }
}

__global__ void k_scatter(const int* __restrict__ groups, int E, int nChunks) {
    int c = blockIdx.x * blockDim.x + threadIdx.x;
    if (c >= nChunks) return;
    int o0 = d_chunkOff[c * 3 + 0];
    int o1 = d_chunkOff[c * 3 + 1];
    int o2 = d_chunkOff[c * 3 + 2];
    int s = c * CHUNK, e = s + CHUNK; if (e > E) e = E;
    for (int i = s; i < e; i++) {
        int g = groups[i];
        int p = (g == 0) ? o0++ : (g == 1) ? o1++ : o2++;
        d_perm[p] = i;
    }
}

// ---------------------------------------------------------------------------
// Main fused kernel. One CTA per 64-edge tile, 128 threads, thread tile 8x8.
// Static smem union (phase2 max 38.1 KB < 48 KB, no attribute calls needed).
// B-operand smem reads broadcast across the warp's two ty-halves (free).
// ---------------------------------------------------------------------------

__global__ __launch_bounds__(128) void k_main(
    const float* __restrict__ emb, const int* __restrict__ edges,
    const float* __restrict__ W1, const float* __restrict__ b1,
    const float* __restrict__ lng, const float* __restrict__ lnb,
    const float* __restrict__ W2, const float* __restrict__ b2,
    const float* __restrict__ W3, const float* __restrict__ b3,
    float* __restrict__ out)
{
    __shared__ __align__(16) union {
        struct { float ee[64 * 36]; float w1[32 * 132]; } p1;  // 26.1 KB
        struct { float h[64 * 132]; float w2[16 * 68]; } p2;   // 38.1 KB
    } sm;
    __shared__ int sU[64], sV[64];

    int b = blockIdx.x;
    if (b >= d_tileBase[3]) return;
    int g = (b >= d_tileBase[1]) + (b >= d_tileBase[2]);
    int tileInG = b - d_tileBase[g];
    int tileStart = d_groupStart[g] + tileInG * 64;
    int nE = d_groupStart[g + 1] - tileStart;
    if (nE > 64) nE = 64;

    int tid = threadIdx.x;
    if (tid < 64) {
        int u = 0, v = 0;
        if (tid < nE) {
            int e = d_perm[tileStart + tid];
            u = edges[2 * e];
            v = edges[2 * e + 1];
        }
        sU[tid] = u; sV[tid] = v;
    }
    __syncthreads();

    const int tx = tid & 15, ty = tid >> 4;   // 16 x 8 thread grid

    // acc2[i][p]: rows ty*8+i (i 0..7); pairs p: 0,1 -> cols tx*4+{0,1},{2,3};
    //                                        p: 2,3 -> cols 64+tx*4+{0,1},{2,3}
    unsigned long long acc2[8][4];
#pragma unroll
    for (int i = 0; i < 8; i++)
#pragma unroll
        for (int p = 0; p < 4; p++) acc2[i][p] = 0ull;

    const float* W1g = W1 + (size_t)g * 256 * 128;

    // ---- GEMM1: [64,256] x [256,128], BK = 32 ----
    for (int kb = 0; kb < 256; kb += 32) {
        // ee tile: 64 rows x 8 float4 = 512 float4 (4 per thread)
#pragma unroll
        for (int t = 0; t < 4; t++) {
            int idx = tid + t * 128;        // 0..511
            int r = idx >> 3, q = idx & 7;  // row 0..63, q 0..7
            int node = (kb < 128) ? sU[r] : sV[r];
            int cb = (kb & 127) + q * 4;
            float4 val = *(const float4*)(emb + (size_t)node * 128 + cb);
            *(float4*)(&sm.p1.ee[r * 36 + q * 4]) = val;
        }
        // W1 tile: 32 rows x 32 float4 = 1024 float4 (8 per thread)
#pragma unroll
        for (int t = 0; t < 8; t++) {
            int idx = tid + t * 128;          // 0..1023
            int rr = idx >> 5, q = idx & 31;  // rr 0..31, q 0..31
            float4 val = *(const float4*)(W1g + (size_t)(kb + rr) * 128 + q * 4);
            *(float4*)(&sm.p1.w1[rr * 132 + q * 4]) = val;
        }
        __syncthreads();

#pragma unroll
        for (int kk4 = 0; kk4 < 32; kk4 += 4) {
            float4 a4[8];
#pragma unroll
            for (int i = 0; i < 8; i++)
                a4[i] = *(const float4*)(&sm.p1.ee[(ty * 8 + i) * 36 + kk4]);
            const float* ap = reinterpret_cast<const float*>(a4);
#pragma unroll
            for (int u = 0; u < 4; u++) {
                ulonglong2 bA = *(const ulonglong2*)(&sm.p1.w1[(kk4 + u) * 132 + tx * 4]);
                ulonglong2 bB = *(const ulonglong2*)(&sm.p1.w1[(kk4 + u) * 132 + 64 + tx * 4]);
#pragma unroll
                for (int i = 0; i < 8; i++) {
                    unsigned long long pa = pack2(ap[i * 4 + u]);
                    ffma2(acc2[i][0], pa, bA.x);
                    ffma2(acc2[i][1], pa, bA.y);
                    ffma2(acc2[i][2], pa, bB.x);
                    ffma2(acc2[i][3], pa, bB.y);
                }
            }
        }
        __syncthreads();
    }

    // ---- bias + LayerNorm + exact GELU, write h to smem ----
    float bb1[8], lgv[8], lbv[8];
#pragma unroll
    for (int j = 0; j < 8; j++) {
        int o = (j < 4) ? (tx * 4 + j) : (64 + tx * 4 + (j - 4));
        bb1[j] = b1[g * 128 + o];
        lgv[j] = lng[g * 128 + o];
        lbv[j] = lnb[g * 128 + o];
    }
#pragma unroll
    for (int i = 0; i < 8; i++) {
        float hv[8];
#pragma unroll
        for (int p = 0; p < 4; p++) {
            float2 f = unpack2(acc2[i][p]);
            hv[p * 2] = f.x; hv[p * 2 + 1] = f.y;
        }
        float s = 0.f, s2 = 0.f;
#pragma unroll
        for (int j = 0; j < 8; j++) {
            float h = hv[j] + bb1[j];
            hv[j] = h;
            s += h; s2 += h * h;
        }
#pragma unroll
        for (int m = 1; m < 16; m <<= 1) {   // reduces the 16 tx lanes
            s  += __shfl_xor_sync(0xffffffffu, s,  m);
            s2 += __shfl_xor_sync(0xffffffffu, s2, m);
        }
        float mu  = s * (1.f / 128.f);
        float var = s2 * (1.f / 128.f) - mu * mu;
        float inv = rsqrtf(var + 1e-5f);
        float4 outA, outB;
        float* oa = reinterpret_cast<float*>(&outA);
        float* ob = reinterpret_cast<float*>(&outB);
#pragma unroll
        for (int j = 0; j < 8; j++) {
            float hn = (hv[j] - mu) * inv * lgv[j] + lbv[j];
            float gv = hn * normcdff(hn);      // exact gelu: x * Phi(x)
            if (j < 4) oa[j] = gv; else ob[j - 4] = gv;
        }
        int row = ty * 8 + i;
        *(float4*)(&sm.p2.h[row * 132 + tx * 4]) = outA;
        *(float4*)(&sm.p2.h[row * 132 + 64 + tx * 4]) = outB;
    }

    // ---- GEMM2: [64,128] x [128,64], BK = 16; thread tile 8 rows x 4 cols --
    const float* W2g = W2 + (size_t)g * 128 * 64;
    unsigned long long c2[8][2];
#pragma unroll
    for (int i = 0; i < 8; i++) { c2[i][0] = 0ull; c2[i][1] = 0ull; }

    for (int kb = 0; kb < 128; kb += 16) {
        __syncthreads();  // protects w2 reuse; first iter also orders h writes
#pragma unroll
        for (int t = 0; t < 2; t++) {
            // w2 tile: 16 rows x 16 float4 = 256 float4 (2 per thread)
            int idx = tid + t * 128;
            int rr = idx >> 4, q = idx & 15;
            float4 val = *(const float4*)(W2g + (size_t)(kb + rr) * 64 + q * 4);
            *(float4*)(&sm.p2.w2[rr * 68 + q * 4]) = val;
        }
        __syncthreads();

#pragma unroll
        for (int kk4 = 0; kk4 < 16; kk4 += 4) {
            float4 a4[8];
#pragma unroll
            for (int i = 0; i < 8; i++)
                a4[i] = *(const float4*)(&sm.p2.h[(ty * 8 + i) * 132 + kb + kk4]);
            const float* ap = reinterpret_cast<const float*>(a4);
#pragma unroll
            for (int u = 0; u < 4; u++) {
                ulonglong2 bv = *(const ulonglong2*)(&sm.p2.w2[(kk4 + u) * 68 + tx * 4]);
#pragma unroll
                for (int i = 0; i < 8; i++) {
                    unsigned long long pa = pack2(ap[i * 4 + u]);
                    ffma2(c2[i][0], pa, bv.x);
                    ffma2(c2[i][1], pa, bv.y);
                }
            }
        }
    }

    // ---- bias + GELU + dot W3 + b3, 16-lane reduce, write ----
    float bb2[4], w3v[4];
#pragma unroll
    for (int j = 0; j < 4; j++) {
        bb2[j] = b2[g * 64 + tx * 4 + j];
        w3v[j] = W3[g * 64 + tx * 4 + j];
    }
    float b3v = b3[g];
#pragma unroll
    for (int i = 0; i < 8; i++) {
        float hv[4];
        float2 f0 = unpack2(c2[i][0]);
        float2 f1 = unpack2(c2[i][1]);
        hv[0] = f0.x; hv[1] = f0.y; hv[2] = f1.x; hv[3] = f1.y;
        float p = 0.f;
#pragma unroll
        for (int j = 0; j < 4; j++) {
            float x = hv[j] + bb2[j];
            float gx = x * normcdff(x);
            p = fmaf(gx, w3v[j], p);
        }
#pragma unroll
        for (int m = 1; m < 16; m <<= 1)
            p += __shfl_xor_sync(0xffffffffu, p, m);
        int r = ty * 8 + i;
        if (tx == 0 && r < nE) out[tileStart + r] = p + b3v;
    }
}

// ---------------------------------------------------------------------------

extern "C" void kernel_launch(void* const* d_in, const int* in_sizes, int n_in,
                              void* d_out, int out_size) {
    const float* emb    = (const float*)d_in[0];
    const int*   edges  = (const int*)d_in[1];
    const int*   groups = (const int*)d_in[2];
    const float* W1     = (const float*)d_in[3];
    const float* b1     = (const float*)d_in[4];
    const float* lng    = (const float*)d_in[5];
    const float* lnb    = (const float*)d_in[6];
    const float* W2     = (const float*)d_in[7];
    const float* b2     = (const float*)d_in[8];
    const float* W3     = (const float*)d_in[9];
    const float* b3     = (const float*)d_in[10];
    float* out = (float*)d_out;

    int E = in_sizes[2];
    int nChunks = (E + CHUNK - 1) / CHUNK;

    k_count<<<(nChunks + 255) / 256, 256>>>(groups, E, nChunks);
    k_scan<<<1, SCAN_T>>>(nChunks);
    k_scatter<<<(nChunks + 255) / 256, 256>>>(groups, E, nChunks);

    int maxTiles = (E + 63) / 64 + 3;
    k_main<<<maxTiles, 128>>>(emb, edges, W1, b1, lng, lnb, W2, b2, W3, b3, out);
}